// round 12
// baseline (speedup 1.0000x reference)
#include <cuda_runtime.h>
#include <cuda_fp16.h>
#include <math.h>
#include <float.h>
#include <stdint.h>

// ---------------- problem constants ----------------
#define N_X    2048
#define M_BUF  131072
#define D_DIM  64
#define KK     11                 // keep K+1 smallest
#define SPLITS 9
#define TPS    114                // splits 0-7: 114 tiles, split 8: 112 (both even)
#define TILES_TOTAL (M_BUF / 128) // 1024
#define BX     64                 // x rows per CTA
#define KBIAS  128.0f             // key bias so biased keys are positive halfs

// ---------------- device scratch ----------------
// buf pair-interleaved: g_bp[p*64 + k] = half2(buf[2p][k], buf[2p+1][k])
__device__ __half2 g_bp[(size_t)(M_BUF / 2) * D_DIM];
// x duplicated: g_xd[r*64 + k] = half2(x[r][k], x[r][k])
__device__ __half2 g_xd[(size_t)N_X * D_DIM];
// biased pair norms: g_bnp[p] = half2(bn2[2p]+128, bn2[2p+1]+128)
__device__ __half2 g_bnp[M_BUF / 2];
__device__ unsigned g_cand[(size_t)N_X * SPLITS * KK];

// ---------------- helpers ----------------
__device__ __forceinline__ uint32_t smem_u32(const void* p) {
    uint32_t a;
    asm("{ .reg .u64 t; cvta.to.shared.u64 t, %1; cvt.u32.u64 %0, t; }" : "=r"(a) : "l"(p));
    return a;
}
#define CP_ASYNC16(ds, gp) asm volatile("cp.async.cg.shared.global [%0], [%1], 16;" :: "r"(ds), "l"(gp))
#define CP_COMMIT() asm volatile("cp.async.commit_group;" ::: "memory")
#define CP_WAIT(n)  asm volatile("cp.async.wait_group %0;" :: "n"(n) : "memory")

__device__ __forceinline__ __half2 asH2(unsigned u) { return *reinterpret_cast<__half2*>(&u); }

// sorted ascending insert; v expected <= tk[10] ordering-wise
__device__ __forceinline__ void bubble11(unsigned tk[KK], unsigned v) {
    tk[10] = v;
    #pragma unroll
    for (int s = 10; s >= 1; s--) {
        unsigned lo = min(tk[s - 1], tk[s]);
        unsigned hi = max(tk[s - 1], tk[s]);
        tk[s - 1] = lo; tk[s] = hi;
    }
}

// ---------------- kernel 1: fp16 pack + biased pair norms ----------------
__global__ void prep_kernel(const float* __restrict__ x, const float* __restrict__ buf) {
    int gw = (blockIdx.x * blockDim.x + threadIdx.x) >> 5;
    int lane = threadIdx.x & 31;
    const int NPAIR = M_BUF / 2;
    if (gw >= NPAIR + N_X) return;
    if (gw < NPAIR) {
        const float2 v0 = reinterpret_cast<const float2*>(buf + (size_t)(2 * gw) * D_DIM)[lane];
        const float2 v1 = reinterpret_cast<const float2*>(buf + (size_t)(2 * gw + 1) * D_DIM)[lane];
        __half2* dst = g_bp + (size_t)gw * D_DIM;
        dst[2 * lane]     = __floats2half2_rn(v0.x, v1.x);
        dst[2 * lane + 1] = __floats2half2_rn(v0.y, v1.y);
        float s0 = v0.x * v0.x + v0.y * v0.y;
        float s1 = v1.x * v1.x + v1.y * v1.y;
        #pragma unroll
        for (int o = 16; o > 0; o >>= 1) {
            s0 += __shfl_xor_sync(0xffffffffu, s0, o);
            s1 += __shfl_xor_sync(0xffffffffu, s1, o);
        }
        if (lane == 0) g_bnp[gw] = __floats2half2_rn(s0 + KBIAS, s1 + KBIAS);
    } else {
        int r = gw - NPAIR;
        const float2 v = reinterpret_cast<const float2*>(x + (size_t)r * D_DIM)[lane];
        __half2* dst = g_xd + (size_t)r * D_DIM;
        dst[2 * lane]     = __floats2half2_rn(v.x, v.x);
        dst[2 * lane + 1] = __floats2half2_rn(v.y, v.y);
    }
}

// ---------------- kernel 2: HFMA2 distances + register top-11 ----------------
// smem: XS [0,16384); B0..B3 @16384 + s*17408 (64 pairs x 272B each);
// BN0..3 @86016 + s*256. total 87040. merge phase aliases [0,22528).
#define XS_OFF  0
#define BB_OFF  16384
#define BB_STRIDE 17408
#define BN_OFF  86016
#define PROWB   272
#define SMEM_TOTAL 87040

extern __shared__ unsigned char smem_raw[];

__device__ __forceinline__ void prefetch_tile(uint32_t sb, int tile, int sel, int tid) {
    uint32_t boff = BB_OFF + sel * BB_STRIDE;
    const char* src = (const char*)g_bp + (size_t)tile * 16384;
    #pragma unroll
    for (int ii = 0; ii < 4; ii++) {
        int q = tid + 256 * ii;            // 1024 16B chunks
        int prow = q >> 4, c = q & 15;
        CP_ASYNC16(sb + boff + prow * PROWB + c * 16, src + prow * 256 + c * 16);
    }
    if (tid < 16)
        CP_ASYNC16(sb + BN_OFF + sel * 256 + tid * 16,
                   (const char*)g_bnp + (size_t)tile * 256 + tid * 16);
}

__global__ void __launch_bounds__(256, 2)
pbe_h2() {
    const int tid = threadIdx.x;
    const int i = tid >> 3;                // 0..31: x rows {i, i+32}
    const int j = tid & 7;                 // 0..7: pairs {j + 8n, n=0..7}
    const int xblock = blockIdx.x * BX;
    const int split  = blockIdx.y;
    const int tbeg = split * TPS;
    const int tend = min(tbeg + TPS, TILES_TOTAL);   // even count per split
    const int ntl  = tend - tbeg;

    uint32_t sb = smem_u32(smem_raw);

    // x tile: linear 16KB copy from g_xd
    {
        const char* src = (const char*)g_xd + (size_t)xblock * 256;
        #pragma unroll
        for (int ii = 0; ii < 4; ii++) {
            int q = tid + 256 * ii;
            CP_ASYNC16(sb + XS_OFF + q * 16, src + q * 16);
        }
    }
    // initial pair -> local buffers 0, 1 (buffer index is ALWAYS local: tl & 3)
    prefetch_tile(sb, tbeg,     0, tid);
    prefetch_tile(sb, tbeg + 1, 1, tid);
    CP_COMMIT();

    unsigned tk[2][KK];
    #pragma unroll
    for (int a = 0; a < 2; a++)
        #pragma unroll
        for (int k = 0; k < KK; k++) tk[a][k] = 0xFFFFFFFFu;
    unsigned thr16_0 = 0xFFFFu, thr16_1 = 0xFFFFu;   // tk[a][10] >> 16

    const __half2 m2 = __float2half2_rn(-2.0f);

    // process tiles in pairs: one wait+sync per 2 tiles
    for (int tl0 = 0; tl0 < ntl; tl0 += 2) {
        CP_WAIT(0);                        // local tiles tl0, tl0+1 resident (x too on iter 0)
        __syncthreads();                   // all warps done reading bufs (tl0+2)&3, (tl0+3)&3
        if (tl0 + 2 < ntl) {
            prefetch_tile(sb, tbeg + tl0 + 2, (tl0 + 2) & 3, tid);
            if (tl0 + 3 < ntl) prefetch_tile(sb, tbeg + tl0 + 3, (tl0 + 3) & 3, tid);
        }
        CP_COMMIT();

        #pragma unroll
        for (int u = 0; u < 2; u++) {
            const int tl = tl0 + u;
            const int s_cur = tl & 3;
            const unsigned char* bt = smem_raw + BB_OFF + s_cur * BB_STRIDE;
            const __half2* bnp = (const __half2*)(smem_raw + BN_OFF + s_cur * 256);

            unsigned bnb[8];
            #pragma unroll
            for (int n = 0; n < 8; n++) {
                __half2 h = bnp[j + n * 8];
                bnb[n] = *reinterpret_cast<unsigned*>(&h);
            }

            __half2 acc[2][8];
            #pragma unroll
            for (int a = 0; a < 2; a++)
                #pragma unroll
                for (int n = 0; n < 8; n++) acc[a][n] = __float2half2_rn(0.f);

            #pragma unroll
            for (int cp = 0; cp < 16; cp++) {
                uint4 xw0 = *(const uint4*)(smem_raw + XS_OFF + i * 256 + cp * 16);
                uint4 xw1 = *(const uint4*)(smem_raw + XS_OFF + (i + 32) * 256 + cp * 16);
                {
                    uint4 bw[4];
                    #pragma unroll
                    for (int n = 0; n < 4; n++)
                        bw[n] = *(const uint4*)(bt + (j + n * 8) * PROWB + cp * 16);
                    #pragma unroll
                    for (int n = 0; n < 4; n++) {
                        acc[0][n] = __hfma2(asH2(xw0.x), asH2(bw[n].x), acc[0][n]);
                        acc[0][n] = __hfma2(asH2(xw0.y), asH2(bw[n].y), acc[0][n]);
                        acc[0][n] = __hfma2(asH2(xw0.z), asH2(bw[n].z), acc[0][n]);
                        acc[0][n] = __hfma2(asH2(xw0.w), asH2(bw[n].w), acc[0][n]);
                        acc[1][n] = __hfma2(asH2(xw1.x), asH2(bw[n].x), acc[1][n]);
                        acc[1][n] = __hfma2(asH2(xw1.y), asH2(bw[n].y), acc[1][n]);
                        acc[1][n] = __hfma2(asH2(xw1.z), asH2(bw[n].z), acc[1][n]);
                        acc[1][n] = __hfma2(asH2(xw1.w), asH2(bw[n].w), acc[1][n]);
                    }
                }
                {
                    uint4 bw[4];
                    #pragma unroll
                    for (int n = 0; n < 4; n++)
                        bw[n] = *(const uint4*)(bt + (j + (n + 4) * 8) * PROWB + cp * 16);
                    #pragma unroll
                    for (int n = 0; n < 4; n++) {
                        acc[0][n + 4] = __hfma2(asH2(xw0.x), asH2(bw[n].x), acc[0][n + 4]);
                        acc[0][n + 4] = __hfma2(asH2(xw0.y), asH2(bw[n].y), acc[0][n + 4]);
                        acc[0][n + 4] = __hfma2(asH2(xw0.z), asH2(bw[n].z), acc[0][n + 4]);
                        acc[0][n + 4] = __hfma2(asH2(xw0.w), asH2(bw[n].w), acc[0][n + 4]);
                        acc[1][n + 4] = __hfma2(asH2(xw1.x), asH2(bw[n].x), acc[1][n + 4]);
                        acc[1][n + 4] = __hfma2(asH2(xw1.y), asH2(bw[n].y), acc[1][n + 4]);
                        acc[1][n + 4] = __hfma2(asH2(xw1.z), asH2(bw[n].z), acc[1][n + 4]);
                        acc[1][n + 4] = __hfma2(asH2(xw1.w), asH2(bw[n].w), acc[1][n + 4]);
                    }
                }
            }

            // epilogue: key = bn2b - 2*dot; hot path = u16 compares; lazy pack
            const unsigned locb = (unsigned)(tl * 128 + j * 2);
            #pragma unroll
            for (int n = 0; n < 8; n++) {
                #pragma unroll
                for (int a = 0; a < 2; a++) {
                    __half2 key2 = __hfma2(m2, acc[a][n], asH2(bnb[n]));
                    unsigned cv = *reinterpret_cast<unsigned*>(&key2);
                    unsigned thr = a ? thr16_1 : thr16_0;
                    if ((cv & 0xFFFFu) <= thr) {
                        unsigned lpw = (locb + n * 16) * 0x00010001u + 0x00010000u;
                        bubble11(tk[a], __byte_perm(cv, lpw, 0x1054));
                        if (a) thr16_1 = tk[1][10] >> 16; else thr16_0 = tk[0][10] >> 16;
                        thr = a ? thr16_1 : thr16_0;
                    }
                    if ((cv >> 16) <= thr) {
                        unsigned lpw = (locb + n * 16) * 0x00010001u + 0x00010000u;
                        bubble11(tk[a], __byte_perm(cv, lpw, 0x3276));
                        if (a) thr16_1 = tk[1][10] >> 16; else thr16_0 = tk[0][10] >> 16;
                    }
                }
            }
        }
    }

    // block merge: 8 j-threads per row -> per-(row,split) top-11
    __syncthreads();
    unsigned* csh = (unsigned*)smem_raw;   // [64 rows][8 j][11]
    #pragma unroll
    for (int a = 0; a < 2; a++) {
        int base = ((i + a * 32) * 8 + j) * KK;
        #pragma unroll
        for (int k = 0; k < KK; k++) csh[base + k] = tk[a][k];
    }
    __syncthreads();

    if (tid < BX) {
        const unsigned* src = csh + tid * (8 * KK);
        unsigned best[KK];
        #pragma unroll
        for (int k = 0; k < KK; k++) best[k] = 0xFFFFFFFFu;
        for (int s = 0; s < 8 * KK; s++) {
            unsigned v = src[s];
            if (v < best[10]) bubble11(best, v);
        }
        unsigned* dst = g_cand + ((size_t)(xblock + tid) * SPLITS + split) * KK;
        #pragma unroll
        for (int k = 0; k < KK; k++) dst[k] = best[k];
    }
}

// ---------------- kernel 3: exact fp32 recompute + final reduction ----------
__global__ void __launch_bounds__(128)
finalize_kernel(const float* __restrict__ x, const float* __restrict__ buf,
                float* __restrict__ out) {
    const int row = blockIdx.x;
    const int tid = threadIdx.x;
    __shared__ float4 xr[16];
    __shared__ float sd2[SPLITS * KK];

    if (tid < 16)
        xr[tid] = reinterpret_cast<const float4*>(x + (size_t)row * D_DIM)[tid];
    __syncthreads();

    if (tid < SPLITS * KK) {
        unsigned cand = g_cand[(size_t)row * SPLITS * KK + tid];
        int split = tid / KK;
        int loc = (int)(cand & 0xFFFFu);
        long gidx = (long)split * (TPS * 128) + loc;
        if (gidx >= M_BUF) gidx = M_BUF - 1;   // safety (unreachable)
        const float4* b4 = reinterpret_cast<const float4*>(buf + gidx * D_DIM);
        float s = 0.f;
        #pragma unroll
        for (int q = 0; q < 16; q++) {
            float4 bv = b4[q], xv = xr[q];
            float d0 = xv.x - bv.x, d1 = xv.y - bv.y;
            float d2 = xv.z - bv.z, d3 = xv.w - bv.w;
            s += d0 * d0 + d1 * d1 + d2 * d2 + d3 * d3;
        }
        sd2[tid] = s;
    }
    __syncthreads();

    if (tid == 0) {
        float best[KK];
        float thrv = FLT_MAX; int mi = 0;
        #pragma unroll
        for (int k = 0; k < KK; k++) best[k] = FLT_MAX;
        for (int s = 0; s < SPLITS * KK; s++) {
            float v = sd2[s];
            if (v < thrv) {
                best[mi] = v;
                float m = best[0]; int mj = 0;
                #pragma unroll
                for (int q = 1; q < KK; q++)
                    if (best[q] > m) { m = best[q]; mj = q; }
                thrv = m; mi = mj;
            }
        }
        float ssum = 0.f, rmin = FLT_MAX;
        #pragma unroll
        for (int k = 0; k < KK; k++) {
            float r = sqrtf(best[k]);
            ssum += r;
            rmin = fminf(rmin, r);
        }
        out[row] = log1pf((ssum - rmin) * 0.1f);   // drop self-match, mean of 10
    }
}

// ---------------------------------------------------------------------------
extern "C" void kernel_launch(void* const* d_in, const int* in_sizes, int n_in,
                              void* d_out, int out_size) {
    const float* x   = (const float*)d_in[0];
    const float* buf = (const float*)d_in[1];
    if (n_in >= 2 && in_sizes[0] != N_X * D_DIM) {
        const float* t = x; x = buf; buf = t;
    }

    cudaFuncSetAttribute(pbe_h2, cudaFuncAttributeMaxDynamicSharedMemorySize, SMEM_TOTAL);

    int total_warps = M_BUF / 2 + N_X;
    prep_kernel<<<(total_warps * 32 + 255) / 256, 256>>>(x, buf);
    pbe_h2<<<dim3(N_X / BX, SPLITS), 256, SMEM_TOTAL>>>();
    finalize_kernel<<<N_X, 128>>>(x, buf, (float*)d_out);
}

// round 16
// speedup vs baseline: 4.0123x; 4.0123x over previous
#include <cuda_runtime.h>
#include <cuda_fp16.h>
#include <math.h>
#include <float.h>
#include <stdint.h>

// ---------------- problem constants ----------------
#define N_X    2048
#define M_BUF  131072
#define D_DIM  64
#define KK     11                 // keep K+1 smallest
#define SPLITS 9
#define TPS    114                // tiles per split (last split: 112)
#define TILES_TOTAL (M_BUF / 128) // 1024
#define BX     64                 // x rows per CTA
#define KBIAS  128.0f             // key bias so biased keys are positive halfs

// ---------------- device scratch ----------------
// buf pair-interleaved: g_bp[p*64 + k] = half2(buf[2p][k], buf[2p+1][k])
__device__ __half2 g_bp[(size_t)(M_BUF / 2) * D_DIM];
// x duplicated: g_xd[r*64 + k] = half2(x[r][k], x[r][k])
__device__ __half2 g_xd[(size_t)N_X * D_DIM];
// biased pair norms: g_bnp[p] = half2(bn2[2p]+128, bn2[2p+1]+128)
__device__ __half2 g_bnp[M_BUF / 2];
__device__ unsigned g_cand[(size_t)N_X * SPLITS * KK];

// ---------------- helpers ----------------
__device__ __forceinline__ uint32_t smem_u32(const void* p) {
    uint32_t a;
    asm("{ .reg .u64 t; cvta.to.shared.u64 t, %1; cvt.u32.u64 %0, t; }" : "=r"(a) : "l"(p));
    return a;
}
#define CP_ASYNC16(ds, gp) asm volatile("cp.async.cg.shared.global [%0], [%1], 16;" :: "r"(ds), "l"(gp))
#define CP_COMMIT() asm volatile("cp.async.commit_group;" ::: "memory")
#define CP_WAIT(n)  asm volatile("cp.async.wait_group %0;" :: "n"(n) : "memory")

__device__ __forceinline__ __half2 asH2(unsigned u) { return *reinterpret_cast<__half2*>(&u); }

// sorted ascending insert; v expected <= tk[10] ordering-wise
__device__ __forceinline__ void bubble11(unsigned tk[KK], unsigned v) {
    tk[10] = v;
    #pragma unroll
    for (int s = 10; s >= 1; s--) {
        unsigned lo = min(tk[s - 1], tk[s]);
        unsigned hi = max(tk[s - 1], tk[s]);
        tk[s - 1] = lo; tk[s] = hi;
    }
}

// ---------------- kernel 1: fp16 pack + biased pair norms ----------------
__global__ void prep_kernel(const float* __restrict__ x, const float* __restrict__ buf) {
    int gw = (blockIdx.x * blockDim.x + threadIdx.x) >> 5;
    int lane = threadIdx.x & 31;
    const int NPAIR = M_BUF / 2;
    if (gw >= NPAIR + N_X) return;
    if (gw < NPAIR) {
        const float2 v0 = reinterpret_cast<const float2*>(buf + (size_t)(2 * gw) * D_DIM)[lane];
        const float2 v1 = reinterpret_cast<const float2*>(buf + (size_t)(2 * gw + 1) * D_DIM)[lane];
        __half2* dst = g_bp + (size_t)gw * D_DIM;
        dst[2 * lane]     = __floats2half2_rn(v0.x, v1.x);
        dst[2 * lane + 1] = __floats2half2_rn(v0.y, v1.y);
        float s0 = v0.x * v0.x + v0.y * v0.y;
        float s1 = v1.x * v1.x + v1.y * v1.y;
        #pragma unroll
        for (int o = 16; o > 0; o >>= 1) {
            s0 += __shfl_xor_sync(0xffffffffu, s0, o);
            s1 += __shfl_xor_sync(0xffffffffu, s1, o);
        }
        if (lane == 0) g_bnp[gw] = __floats2half2_rn(s0 + KBIAS, s1 + KBIAS);
    } else {
        int r = gw - NPAIR;
        const float2 v = reinterpret_cast<const float2*>(x + (size_t)r * D_DIM)[lane];
        __half2* dst = g_xd + (size_t)r * D_DIM;
        dst[2 * lane]     = __floats2half2_rn(v.x, v.x);
        dst[2 * lane + 1] = __floats2half2_rn(v.y, v.y);
    }
}

// ---------------- kernel 2: HFMA2 distances + register top-11 ----------------
// smem: XS [0,16384); B0/B1/B2 @16384+17408*s (64 pairs x 272B);
// BN0/1/2 @68608+256*s. total 69632. merge phase aliases [0,22528).
#define XS_OFF  0
#define BB_OFF  16384
#define BB_STRIDE 17408
#define BN_OFF  68608
#define PROWB   272
#define SMEM_TOTAL 69632

extern __shared__ unsigned char smem_raw[];

__device__ __forceinline__ void prefetch_tile(uint32_t sb, int tile, int sel, int tid) {
    uint32_t boff = BB_OFF + sel * BB_STRIDE;
    const char* src = (const char*)g_bp + (size_t)tile * 16384;
    #pragma unroll
    for (int ii = 0; ii < 4; ii++) {
        int q = tid + 256 * ii;            // 1024 16B chunks
        int prow = q >> 4, c = q & 15;
        CP_ASYNC16(sb + boff + prow * PROWB + c * 16, src + prow * 256 + c * 16);
    }
    if (tid < 16)
        CP_ASYNC16(sb + BN_OFF + sel * 256 + tid * 16,
                   (const char*)g_bnp + (size_t)tile * 256 + tid * 16);
}

__global__ void __launch_bounds__(256, 2)
pbe_h2() {
    const int tid = threadIdx.x;
    const int i = tid >> 3;                // 0..31: x rows {i, i+32}
    const int j = tid & 7;                 // 0..7: pairs {j + 8n, n=0..7}
    const int xblock = blockIdx.x * BX;
    const int split  = blockIdx.y;
    const int tbeg = split * TPS;
    const int tend = min(tbeg + TPS, TILES_TOTAL);

    uint32_t sb = smem_u32(smem_raw);

    // x tile: linear 16KB copy from g_xd
    {
        const char* src = (const char*)g_xd + (size_t)xblock * 256;
        #pragma unroll
        for (int ii = 0; ii < 4; ii++) {
            int q = tid + 256 * ii;
            CP_ASYNC16(sb + XS_OFF + q * 16, src + q * 16);
        }
    }
    prefetch_tile(sb, tbeg, 0, tid);
    CP_COMMIT();
    prefetch_tile(sb, tbeg + 1, 1, tid);
    CP_COMMIT();

    unsigned tk[2][KK];
    #pragma unroll
    for (int a = 0; a < 2; a++)
        #pragma unroll
        for (int k = 0; k < KK; k++) tk[a][k] = 0xFFFFFFFFu;
    unsigned thr16_0 = 0xFFFFu, thr16_1 = 0xFFFFu;   // tk[a][10] >> 16

    const __half2 m2 = __float2half2_rn(-2.0f);

    int s_cur = 0;
    for (int t = tbeg; t < tend; t++) {
        const int tl = t - tbeg;
        CP_WAIT(1);                        // tile t resident
        __syncthreads();                   // all warps done with buf s_cur's previous use
        {
            int s_nxt = s_cur + 2; if (s_nxt >= 3) s_nxt -= 3;
            if (t + 2 < tend) prefetch_tile(sb, t + 2, s_nxt, tid);
            CP_COMMIT();
        }

        const unsigned char* bt = smem_raw + BB_OFF + s_cur * BB_STRIDE;
        const __half2* bnp = (const __half2*)(smem_raw + BN_OFF + s_cur * 256);

        unsigned bnb[8];
        #pragma unroll
        for (int n = 0; n < 8; n++) {
            __half2 h = bnp[j + n * 8];
            bnb[n] = *reinterpret_cast<unsigned*>(&h);
        }

        __half2 acc[2][8];
        #pragma unroll
        for (int a = 0; a < 2; a++)
            #pragma unroll
            for (int n = 0; n < 8; n++) acc[a][n] = __float2half2_rn(0.f);

        #pragma unroll
        for (int cp = 0; cp < 16; cp++) {
            uint4 xw0 = *(const uint4*)(smem_raw + XS_OFF + i * 256 + cp * 16);
            uint4 xw1 = *(const uint4*)(smem_raw + XS_OFF + (i + 32) * 256 + cp * 16);
            // first half of pairs
            {
                uint4 bw[4];
                #pragma unroll
                for (int n = 0; n < 4; n++)
                    bw[n] = *(const uint4*)(bt + (j + n * 8) * PROWB + cp * 16);
                #pragma unroll
                for (int n = 0; n < 4; n++) {
                    acc[0][n] = __hfma2(asH2(xw0.x), asH2(bw[n].x), acc[0][n]);
                    acc[0][n] = __hfma2(asH2(xw0.y), asH2(bw[n].y), acc[0][n]);
                    acc[0][n] = __hfma2(asH2(xw0.z), asH2(bw[n].z), acc[0][n]);
                    acc[0][n] = __hfma2(asH2(xw0.w), asH2(bw[n].w), acc[0][n]);
                    acc[1][n] = __hfma2(asH2(xw1.x), asH2(bw[n].x), acc[1][n]);
                    acc[1][n] = __hfma2(asH2(xw1.y), asH2(bw[n].y), acc[1][n]);
                    acc[1][n] = __hfma2(asH2(xw1.z), asH2(bw[n].z), acc[1][n]);
                    acc[1][n] = __hfma2(asH2(xw1.w), asH2(bw[n].w), acc[1][n]);
                }
            }
            // second half of pairs
            {
                uint4 bw[4];
                #pragma unroll
                for (int n = 0; n < 4; n++)
                    bw[n] = *(const uint4*)(bt + (j + (n + 4) * 8) * PROWB + cp * 16);
                #pragma unroll
                for (int n = 0; n < 4; n++) {
                    acc[0][n + 4] = __hfma2(asH2(xw0.x), asH2(bw[n].x), acc[0][n + 4]);
                    acc[0][n + 4] = __hfma2(asH2(xw0.y), asH2(bw[n].y), acc[0][n + 4]);
                    acc[0][n + 4] = __hfma2(asH2(xw0.z), asH2(bw[n].z), acc[0][n + 4]);
                    acc[0][n + 4] = __hfma2(asH2(xw0.w), asH2(bw[n].w), acc[0][n + 4]);
                    acc[1][n + 4] = __hfma2(asH2(xw1.x), asH2(bw[n].x), acc[1][n + 4]);
                    acc[1][n + 4] = __hfma2(asH2(xw1.y), asH2(bw[n].y), acc[1][n + 4]);
                    acc[1][n + 4] = __hfma2(asH2(xw1.z), asH2(bw[n].z), acc[1][n + 4]);
                    acc[1][n + 4] = __hfma2(asH2(xw1.w), asH2(bw[n].w), acc[1][n + 4]);
                }
            }
        }

        // epilogue: key = bn2b - 2*dot (half2); hot path = u16 compares only;
        // PRMT pack + loc computed lazily on insert.
        const unsigned locb = (unsigned)(tl * 128 + j * 2);
        #pragma unroll
        for (int n = 0; n < 8; n++) {
            #pragma unroll
            for (int a = 0; a < 2; a++) {
                __half2 key2 = __hfma2(m2, acc[a][n], asH2(bnb[n]));
                unsigned cv = *reinterpret_cast<unsigned*>(&key2);
                unsigned thr = a ? thr16_1 : thr16_0;
                if ((cv & 0xFFFFu) <= thr) {
                    unsigned lpw = (locb + n * 16) * 0x00010001u + 0x00010000u;
                    bubble11(tk[a], __byte_perm(cv, lpw, 0x1054));
                    if (a) thr16_1 = tk[1][10] >> 16; else thr16_0 = tk[0][10] >> 16;
                    thr = a ? thr16_1 : thr16_0;
                }
                if ((cv >> 16) <= thr) {
                    unsigned lpw = (locb + n * 16) * 0x00010001u + 0x00010000u;
                    bubble11(tk[a], __byte_perm(cv, lpw, 0x3276));
                    if (a) thr16_1 = tk[1][10] >> 16; else thr16_0 = tk[0][10] >> 16;
                }
            }
        }
        s_cur = (s_cur == 2) ? 0 : s_cur + 1;
    }

    // block merge: 8 j-threads per row -> per-(row,split) top-11
    __syncthreads();
    unsigned* csh = (unsigned*)smem_raw;   // [64 rows][8 j][11]
    #pragma unroll
    for (int a = 0; a < 2; a++) {
        int base = ((i + a * 32) * 8 + j) * KK;
        #pragma unroll
        for (int k = 0; k < KK; k++) csh[base + k] = tk[a][k];
    }
    __syncthreads();

    if (tid < BX) {
        const unsigned* src = csh + tid * (8 * KK);
        unsigned best[KK];
        #pragma unroll
        for (int k = 0; k < KK; k++) best[k] = 0xFFFFFFFFu;
        for (int s = 0; s < 8 * KK; s++) {
            unsigned v = src[s];
            if (v < best[10]) bubble11(best, v);
        }
        unsigned* dst = g_cand + ((size_t)(xblock + tid) * SPLITS + split) * KK;
        #pragma unroll
        for (int k = 0; k < KK; k++) dst[k] = best[k];
    }
}

// ---------------- kernel 3: exact fp32 recompute + final reduction ----------
__global__ void __launch_bounds__(128)
finalize_kernel(const float* __restrict__ x, const float* __restrict__ buf,
                float* __restrict__ out) {
    const int row = blockIdx.x;
    const int tid = threadIdx.x;
    __shared__ float4 xr[16];
    __shared__ float sd2[SPLITS * KK];

    if (tid < 16)
        xr[tid] = reinterpret_cast<const float4*>(x + (size_t)row * D_DIM)[tid];
    __syncthreads();

    if (tid < SPLITS * KK) {
        unsigned cand = g_cand[(size_t)row * SPLITS * KK + tid];
        int split = tid / KK;
        int loc = (int)(cand & 0xFFFFu);
        long gidx = (long)split * (TPS * 128) + loc;
        if (gidx >= M_BUF) gidx = M_BUF - 1;   // safety (unreachable)
        const float4* b4 = reinterpret_cast<const float4*>(buf + gidx * D_DIM);
        float s = 0.f;
        #pragma unroll
        for (int q = 0; q < 16; q++) {
            float4 bv = b4[q], xv = xr[q];
            float d0 = xv.x - bv.x, d1 = xv.y - bv.y;
            float d2 = xv.z - bv.z, d3 = xv.w - bv.w;
            s += d0 * d0 + d1 * d1 + d2 * d2 + d3 * d3;
        }
        sd2[tid] = s;
    }
    __syncthreads();

    if (tid == 0) {
        float best[KK];
        float thrv = FLT_MAX; int mi = 0;
        #pragma unroll
        for (int k = 0; k < KK; k++) best[k] = FLT_MAX;
        for (int s = 0; s < SPLITS * KK; s++) {
            float v = sd2[s];
            if (v < thrv) {
                best[mi] = v;
                float m = best[0]; int mj = 0;
                #pragma unroll
                for (int q = 1; q < KK; q++)
                    if (best[q] > m) { m = best[q]; mj = q; }
                thrv = m; mi = mj;
            }
        }
        float ssum = 0.f, rmin = FLT_MAX;
        #pragma unroll
        for (int k = 0; k < KK; k++) {
            float r = sqrtf(best[k]);
            ssum += r;
            rmin = fminf(rmin, r);
        }
        out[row] = log1pf((ssum - rmin) * 0.1f);   // drop self-match, mean of 10
    }
}

// ---------------------------------------------------------------------------
extern "C" void kernel_launch(void* const* d_in, const int* in_sizes, int n_in,
                              void* d_out, int out_size) {
    const float* x   = (const float*)d_in[0];
    const float* buf = (const float*)d_in[1];
    if (n_in >= 2 && in_sizes[0] != N_X * D_DIM) {
        const float* t = x; x = buf; buf = t;
    }

    cudaFuncSetAttribute(pbe_h2, cudaFuncAttributeMaxDynamicSharedMemorySize, SMEM_TOTAL);

    int total_warps = M_BUF / 2 + N_X;
    prep_kernel<<<(total_warps * 32 + 255) / 256, 256>>>(x, buf);
    pbe_h2<<<dim3(N_X / BX, SPLITS), 256, SMEM_TOTAL>>>();
    finalize_kernel<<<N_X, 128>>>(x, buf, (float*)d_out);
}